// round 14
// baseline (speedup 1.0000x reference)
#include <cuda_runtime.h>
#include <cuda_bf16.h>

#define HW      589824      // 768*768
#define NG      147456      // HW/4 int4-groups per batch
#define BPB     92          // blocks per batch (8*92=736 blocks ~ one 5-occ wave)
#define TPB     128
#define NB      8
#define NC      9           // channels
#define NCLS    8           // accumulated classes (class 0 dropped: unused in loss)
#define NPACK   5           // 10 values (9 ch + count) as float2
#define NOUT    80          // 8 classes * 10 values

__device__ float g_part[NB * BPB * NOUT];
__device__ float g_tot[NB * NOUT];
__device__ int   g_bcnt[NB];
__device__ int   g_fcnt;

__global__ void __launch_bounds__(TPB, 5) fused_kernel(
    const int* __restrict__ masks, const float* __restrict__ outs,
    float* __restrict__ out)
{
    // per-lane-private accumulators: [warp][class(1..8)][pack][lane]
    __shared__ float2 sh[4 * NCLS * NPACK * 32];   // 40960 B
    __shared__ int s_last;
    __shared__ float per[64], pres[64];

    const int tid  = threadIdx.x;
    const int lane = tid & 31;
    const int w    = tid >> 5;
    const int b    = blockIdx.y;
    const int blk  = blockIdx.x;

    // lane-private zero (no barrier needed before use)
    #pragma unroll
    for (int m = 0; m < NCLS; m++)
        #pragma unroll
        for (int p = 0; p < NPACK; p++)
            sh[((w * NCLS + m) * NPACK + p) * 32 + lane] = make_float2(0.f, 0.f);

    const int4*   m4 = (const int4*)(masks + (size_t)b * HW);
    const float4* o4 = (const float4*)(outs + (size_t)b * NC * HW);
    const int stride = BPB * TPB;

    int g = blk * TPB + tid;
    int4   mmA;
    float4 vA[NC];
    if (g < NG) {
        mmA = m4[g];
        #pragma unroll
        for (int c = 0; c < NC; c++) vA[c] = o4[(size_t)c * NG + g];
    }

    #pragma unroll 1
    for (; g < NG; g += stride) {
        int gn = g + stride;
        int4   mmB;
        float4 vB[NC];
        if (gn < NG) {                        // prefetch next tile
            mmB = m4[gn];
            #pragma unroll
            for (int c = 0; c < NC; c++) vB[c] = o4[(size_t)c * NG + gn];
        }

        #pragma unroll
        for (int j = 0; j < 4; j++) {
            int m = (j == 0) ? mmA.x : (j == 1) ? mmA.y : (j == 2) ? mmA.z : mmA.w;
            float w0 = (m != 0) ? 1.0f : 0.0f;       // class 0 contributes nothing
            int ms = max(m, 1) - 1;                  // slot 0..7 for classes 1..8
            float2* base = sh + ((w * NCLS + ms) * NPACK) * 32 + lane;

            float pv[10];
            #pragma unroll
            for (int c = 0; c < NC; c++) {
                float e = (j == 0) ? vA[c].x : (j == 1) ? vA[c].y
                        : (j == 2) ? vA[c].z : vA[c].w;
                pv[c] = e * w0;
            }
            pv[9] = w0;                              // count channel

            #pragma unroll
            for (int p = 0; p < NPACK; p++) {
                float2 a = base[p * 32];
                a.x += pv[2 * p];
                a.y += pv[2 * p + 1];
                base[p * 32] = a;
            }
        }

        mmA = mmB;
        #pragma unroll
        for (int c = 0; c < NC; c++) vA[c] = vB[c];
    }
    __syncthreads();

    // fold warp regions 1..3 into warp 0's region (all 128 threads)
    for (int i = tid; i < NCLS * NPACK * 32; i += TPB) {
        float2 a = sh[i];
        float2 x = sh[i + 1280], y = sh[i + 2560], z = sh[i + 3840];
        a.x += x.x + y.x + z.x;
        a.y += x.y + y.y + z.y;
        sh[i] = a;
    }
    __syncthreads();

    // 32-lane sums -> 80 partials for this block
    if (tid < NOUT) {
        int m = tid / 10, cc = tid % 10, p = cc >> 1, hf = cc & 1;
        float s = 0.0f;
        #pragma unroll 8
        for (int l = 0; l < 32; l++) {
            float2 a = sh[(m * NPACK + p) * 32 + l];
            s += hf ? a.y : a.x;
        }
        g_part[((size_t)(b * BPB + blk)) * NOUT + tid] = s;
    }
    __threadfence();
    __syncthreads();
    if (tid == 0) s_last = (atomicAdd(&g_bcnt[b], 1) == BPB - 1);
    __syncthreads();
    if (!s_last) return;

    // ── per-batch reducer (8 in parallel, one per batch) ──
    __threadfence();
    if (tid < NOUT) {
        float s = 0.0f;
        #pragma unroll 4
        for (int k = 0; k < BPB; k++)
            s += g_part[((size_t)(b * BPB + k)) * NOUT + tid];
        g_tot[b * NOUT + tid] = s;
    }
    __threadfence();
    __syncthreads();
    if (tid == 0) s_last = (atomicAdd(&g_fcnt, 1) == NB - 1);
    __syncthreads();
    if (!s_last) return;

    // ── global final block: log-softmax loss over 64 protos ──
    __threadfence();
    if (tid < 64) {
        int bb = tid / 8, k = tid % 8;               // class index k -> class k+1
        float cnt   = g_tot[bb * NOUT + k * 10 + 9];
        float denom = fmaxf(cnt, 1.0f);
        float p[NC], mx = -1e30f;
        #pragma unroll
        for (int c = 0; c < NC; c++) {
            p[c] = g_tot[bb * NOUT + k * 10 + c] / denom;
            mx = fmaxf(mx, p[c]);
        }
        float se = 0.0f;
        #pragma unroll
        for (int c = 0; c < NC; c++) se += expf(p[c] - mx);
        float lse = mx + logf(se);
        float l = 0.0f;
        #pragma unroll
        for (int c = 0; c < NC; c++) {
            float tgt = (c == k + 1) ? 0.9f : 0.0125f;
            l += tgt * (p[c] - lse);
        }
        bool present = cnt > 0.0f;
        per[tid]  = present ? -l   : 0.0f;
        pres[tid] = present ? 1.0f : 0.0f;
    }
    __syncthreads();
    if (tid == 0) {
        float L = 0.0f, P = 0.0f;
        #pragma unroll
        for (int i = 0; i < 64; i++) { L += per[i]; P += pres[i]; }
        out[0] = L / fmaxf(P, 1.0f);
        g_fcnt = 0;
    }
    if (tid < NB) g_bcnt[tid] = 0;
}

extern "C" void kernel_launch(void* const* d_in, const int* in_sizes, int n_in,
                              void* d_out, int out_size)
{
    const int* masks;
    const float* outs;
    if (in_sizes[0] == NB * HW) {
        masks = (const int*)d_in[0];
        outs  = (const float*)d_in[1];
    } else {
        masks = (const int*)d_in[1];
        outs  = (const float*)d_in[0];
    }
    float* out = (float*)d_out;

    static bool configured = false;
    if (!configured) {
        cudaFuncSetAttribute(fused_kernel,
                             cudaFuncAttributePreferredSharedMemoryCarveout, 100);
        configured = true;
    }

    dim3 grid(BPB, NB);
    fused_kernel<<<grid, TPB>>>(masks, outs, out);
}